// round 9
// baseline (speedup 1.0000x reference)
#include <cuda_runtime.h>
#include <cuda_fp16.h>
#include <cstdint>

#define NS     25
#define NQ     200
#define NITEM  (NS + NQ)        // 225
#define FF     80
#define DD     512
#define WAY    5
#define BLK    128
#define NBLK   10               // packed upper-tri 128x128 blocks of 4x4 grid
#define BLKSZ  (BLK * BLK)      // 16384 elems per block
#define KPACK  (NBLK * BLKSZ)   // 163840
#define PITCH  136              // smem pitch (halves) for X slices
#define SLICE  (FF * PITCH)     // halves per slice buffer
#define NUNIT  (NBLK * NITEM)   // 2250
#define GGRID  296              // persistent CTAs (2/SM)

// -------- scratch (__device__ globals; no allocations allowed) --------------
__device__ __half g_Sn[NS * FF * DD];        // 2 MB   normalized supports
__device__ __half g_Qn[NQ * FF * DD];        // 16.4MB normalized queries
__device__ float  g_Gc[WAY][KPACK];          // class Grams fp32, frag order (3.3MB)
__device__ __half g_Hp[NQ][KPACK];           // query Grams fp16, frag order
__device__ float  g_bar[NITEM][DD];          // per-item feature-row sums
__device__ float  g_S2[WAY][NQ];

__constant__ int c_bi[NBLK] = {0,0,0,0,1,1,1,2,2,3};
__constant__ int c_bj[NBLK] = {0,1,2,3,1,2,3,2,3,3};

// ---------------------------------------------------------------------------
// K1 (fused): zero g_Gc/g_S2 (grid-stride), then per-item normalize + rowsum.
// One CTA per item.
// ---------------------------------------------------------------------------
__global__ void __launch_bounds__(256) norm_kernel(
    const float* __restrict__ sg, const float* __restrict__ sl,
    const float* __restrict__ qg, const float* __restrict__ ql)
{
    __shared__ float snorm[FF];
    const int item = blockIdx.x;
    const int tid  = threadIdx.x;
    const int lane = tid & 31;
    const int warp = tid >> 5;

    // ---- zero accumulators (stream-ordered before gram) ----
    {
        float4 z = {0.f, 0.f, 0.f, 0.f};
        float4* gc = (float4*)&g_Gc[0][0];
        const int n4 = WAY * KPACK / 4;                 // 204800
        for (int i = item * 256 + tid; i < n4; i += NITEM * 256) gc[i] = z;
        for (int i = item * 256 + tid; i < WAY * NQ; i += NITEM * 256)
            (&g_S2[0][0])[i] = 0.f;
    }

    const float* gbase;
    const float* lbase;
    __half* dst;
    if (item < NS) {
        gbase = sg + (size_t)item * 16 * DD;
        lbase = sl + (size_t)item * 64 * DD;
        dst   = g_Sn + (size_t)item * FF * DD;
    } else {
        int q = item - NS;
        gbase = qg + (size_t)q * 16 * DD;
        lbase = ql + (size_t)q * 64 * DD;
        dst   = g_Qn + (size_t)q * FF * DD;
    }

    // ---- pass 1: per-row 1/||x|| ----
    for (int f = warp; f < FF; f += 8) {
        const float4* src = (const float4*)((f < 16) ? gbase + (size_t)f * DD
                                                     : lbase + (size_t)(f - 16) * DD);
        float ss = 0.f;
#pragma unroll
        for (int i = 0; i < 4; i++) {
            float4 v = src[lane + 32 * i];
            ss += v.x * v.x + v.y * v.y + v.z * v.z + v.w * v.w;
        }
#pragma unroll
        for (int o = 16; o; o >>= 1) ss += __shfl_xor_sync(0xFFFFFFFFu, ss, o);
        if (lane == 0) snorm[f] = rsqrtf(fmaxf(ss, 1e-24f));
    }
    __syncthreads();

    // ---- pass 2: scale + fp16 store + column sums ----
    float sx = 0.f, sy = 0.f;
#pragma unroll 4
    for (int f = 0; f < FF; f++) {
        const float2* src = (const float2*)((f < 16) ? gbase + (size_t)f * DD
                                                     : lbase + (size_t)(f - 16) * DD);
        float2 v = src[tid];
        float rn = snorm[f];
        float a = v.x * rn, b = v.y * rn;
        sx += a; sy += b;
        *(__half2*)(dst + (size_t)f * DD + 2 * tid) = __floats2half2_rn(a, b);
    }
    g_bar[item][2 * tid + 0] = sx;
    g_bar[item][2 * tid + 1] = sy;
}

// ---------------------------------------------------------------------------
// shared mma machinery
// ---------------------------------------------------------------------------
__device__ __forceinline__ void ldsm_x4_t(uint32_t (&r)[4], const __half* p)
{
    uint32_t a = (uint32_t)__cvta_generic_to_shared(p);
    asm volatile("ldmatrix.sync.aligned.m8n8.x4.trans.shared.b16 {%0,%1,%2,%3}, [%4];"
                 : "=r"(r[0]), "=r"(r[1]), "=r"(r[2]), "=r"(r[3]) : "r"(a));
}

__device__ __forceinline__ void mma16816(float (&d)[4], const uint32_t (&a)[4],
                                         uint32_t b0, uint32_t b1)
{
    asm volatile("mma.sync.aligned.m16n8k16.row.col.f32.f16.f16.f32 "
                 "{%0,%1,%2,%3},{%4,%5,%6,%7},{%8,%9},{%0,%1,%2,%3};"
                 : "+f"(d[0]), "+f"(d[1]), "+f"(d[2]), "+f"(d[3])
                 : "r"(a[0]), "r"(a[1]), "r"(a[2]), "r"(a[3]), "r"(b0), "r"(b1));
}

__device__ __forceinline__ void gram_block_mma(
    const __half* sX0, const __half* pB, float (&acc)[2][8][4],
    int m_base, int n_base, int lane)
{
    const int a_krow = ((lane >> 4) << 3) + (lane & 7);
    const int a_coff = ((lane >> 3) & 1) << 3;
    const int b_krow = (((lane >> 3) & 1) << 3) + (lane & 7);
    const int b_coff = (lane >> 4) << 3;

#pragma unroll
    for (int k16 = 0; k16 < FF / 16; k16++) {
        const int k0 = k16 * 16;
        uint32_t a[2][4];
#pragma unroll
        for (int mt = 0; mt < 2; mt++)
            ldsm_x4_t(a[mt], &sX0[(k0 + a_krow) * PITCH + m_base + mt * 16 + a_coff]);
#pragma unroll
        for (int nt = 0; nt < 4; nt++) {
            uint32_t bf[4];
            ldsm_x4_t(bf, &pB[(k0 + b_krow) * PITCH + n_base + nt * 16 + b_coff]);
#pragma unroll
            for (int mt = 0; mt < 2; mt++) {
                mma16816(acc[mt][2 * nt + 0], a[mt], bf[0], bf[1]);
                mma16816(acc[mt][2 * nt + 1], a[mt], bf[2], bf[3]);
            }
        }
    }
}

// ---------------------------------------------------------------------------
// K2: persistent pipelined Gram kernel. 2250 units = (item, block).
// Query units -> fp16 H store; support units -> fp32 atomicAdd into g_Gc[label].
// ---------------------------------------------------------------------------
extern __shared__ char dynsmem[];

__device__ __forceinline__ void issue_unit_load(int u, int stage, int tid)
{
    const int item = u / NBLK, b = u % NBLK;
    const int bi = c_bi[b], bj = c_bj[b];
    const __half* base = (item < NS) ? g_Sn + (size_t)item * FF * DD
                                     : g_Qn + (size_t)(item - NS) * FF * DD;
    __half* s0 = (__half*)dynsmem + stage * 2 * SLICE;
    const int nch = (bi == bj) ? 1280 : 2560;
    for (int ch = tid; ch < nch; ch += 256) {
        int tile = (ch >= 1280) ? 1 : 0;
        int rem  = ch - tile * 1280;
        int r = rem >> 4, cc = rem & 15;
        int colblk = tile ? bj : bi;
        const __half* src = base + (size_t)r * DD + colblk * 128 + cc * 8;
        __half* dsts = s0 + tile * SLICE + r * PITCH + cc * 8;
        uint32_t dst = (uint32_t)__cvta_generic_to_shared(dsts);
        asm volatile("cp.async.cg.shared.global [%0], [%1], 16;" :: "r"(dst), "l"(src));
    }
    asm volatile("cp.async.commit_group;");
}

__global__ void __launch_bounds__(256, 2) gram_kernel(const long long* __restrict__ labels)
{
    const int tid  = threadIdx.x;
    const int lane = tid & 31;
    const int warp = tid >> 5;
    const int m_base = (warp >> 1) * 32;
    const int n_base = (warp & 1) * 64;

    int u = blockIdx.x;
    if (u >= NUNIT) return;

    issue_unit_load(u, 0, tid);
    int stage = 0;

    for (; u < NUNIT; u += gridDim.x) {
        const int nextu = u + gridDim.x;
        if (nextu < NUNIT) {
            issue_unit_load(nextu, stage ^ 1, tid);
            asm volatile("cp.async.wait_group 1;");
        } else {
            asm volatile("cp.async.wait_group 0;");
        }
        __syncthreads();

        const int item = u / NBLK, b = u % NBLK;
        const bool diag = (c_bi[b] == c_bj[b]);
        const __half* s0 = (const __half*)dynsmem + stage * 2 * SLICE;
        const __half* pB = diag ? s0 : s0 + SLICE;

        float acc[2][8][4];
#pragma unroll
        for (int mt = 0; mt < 2; mt++)
#pragma unroll
            for (int nt = 0; nt < 8; nt++)
#pragma unroll
                for (int i = 0; i < 4; i++) acc[mt][nt][i] = 0.f;

        gram_block_mma(s0, pB, acc, m_base, n_base, lane);

        if (item < NS) {
            // support unit: fp32 atomic accumulate into class Gram (x2 offdiag)
            const int c = (int)labels[item];
            const float scale = diag ? 1.f : 2.f;
            float* out = g_Gc[c] + (size_t)b * BLKSZ;
#pragma unroll
            for (int j = 0; j < 8; j++) {
                const int mt = j >> 2, nt0 = (j & 3) * 2;
                float* o = out + (size_t)(j * 256 + tid) * 8;
                atomicAdd(o + 0, acc[mt][nt0][0] * scale);
                atomicAdd(o + 1, acc[mt][nt0][1] * scale);
                atomicAdd(o + 2, acc[mt][nt0][2] * scale);
                atomicAdd(o + 3, acc[mt][nt0][3] * scale);
                atomicAdd(o + 4, acc[mt][nt0 + 1][0] * scale);
                atomicAdd(o + 5, acc[mt][nt0 + 1][1] * scale);
                atomicAdd(o + 6, acc[mt][nt0 + 1][2] * scale);
                atomicAdd(o + 7, acc[mt][nt0 + 1][3] * scale);
            }
        } else {
            // query unit: fp16 coalesced H store
            __half* out = g_Hp[item - NS] + (size_t)b * BLKSZ;
#pragma unroll
            for (int j = 0; j < 8; j++) {
                const int mt = j >> 2, nt0 = (j & 3) * 2;
                __half2 h[4];
                h[0] = __floats2half2_rn(acc[mt][nt0][0], acc[mt][nt0][1]);
                h[1] = __floats2half2_rn(acc[mt][nt0][2], acc[mt][nt0][3]);
                h[2] = __floats2half2_rn(acc[mt][nt0 + 1][0], acc[mt][nt0 + 1][1]);
                h[3] = __floats2half2_rn(acc[mt][nt0 + 1][2], acc[mt][nt0 + 1][3]);
                *(int4*)(out + (size_t)(j * 256 + tid) * 8) = *(int4*)h;
            }
        }
        __syncthreads();
        stage ^= 1;
    }
}

// ---------------------------------------------------------------------------
// K3: dot. grid (40 kchunks x 25 query-octets). Gc fp32 loaded once per CTA,
// converted to half2 regs; H streamed coalesced; HFMA2 + butterfly + atomics.
// ---------------------------------------------------------------------------
__global__ void __launch_bounds__(256) dot_kernel()
{
    const int kc   = blockIdx.x;            // 0..39
    const int q0   = blockIdx.y * 8;        // 0..192
    const int tid  = threadIdx.x;
    const int lane = tid & 31;
    const int warp = tid >> 5;
    const int kbase = kc * 4096 + warp * 512 + lane * 8;

    __half2 G[WAY][8];
#pragma unroll
    for (int c = 0; c < WAY; c++) {
        float4 f0 = *(const float4*)&g_Gc[c][kbase];
        float4 f1 = *(const float4*)&g_Gc[c][kbase + 4];
        float4 f2 = *(const float4*)&g_Gc[c][kbase + 256];
        float4 f3 = *(const float4*)&g_Gc[c][kbase + 260];
        G[c][0] = __floats2half2_rn(f0.x, f0.y);
        G[c][1] = __floats2half2_rn(f0.z, f0.w);
        G[c][2] = __floats2half2_rn(f1.x, f1.y);
        G[c][3] = __floats2half2_rn(f1.z, f1.w);
        G[c][4] = __floats2half2_rn(f2.x, f2.y);
        G[c][5] = __floats2half2_rn(f2.z, f2.w);
        G[c][6] = __floats2half2_rn(f3.x, f3.y);
        G[c][7] = __floats2half2_rn(f3.z, f3.w);
    }

    float acc[8][WAY];
#pragma unroll
    for (int qi = 0; qi < 8; qi++)
#pragma unroll
        for (int c = 0; c < WAY; c++) acc[qi][c] = 0.f;

#pragma unroll
    for (int qi = 0; qi < 8; qi++) {
        const __half* Hq = g_Hp[q0 + qi] + kbase;
        __half2 H[8];
        *(int4*)&H[0] = *(const int4*)(Hq);
        *(int4*)&H[4] = *(const int4*)(Hq + 256);
#pragma unroll
        for (int c = 0; c < WAY; c++) {
            __half2 a = __hmul2(G[c][0], H[0]);
#pragma unroll
            for (int j = 1; j < 8; j++) a = __hfma2(G[c][j], H[j], a);
            float2 f = __half22float2(a);
            acc[qi][c] = f.x + f.y;
        }
    }

#pragma unroll
    for (int o = 16; o; o >>= 1)
#pragma unroll
        for (int qi = 0; qi < 8; qi++)
#pragma unroll
            for (int c = 0; c < WAY; c++)
                acc[qi][c] += __shfl_xor_sync(0xFFFFFFFFu, acc[qi][c], o);

    __shared__ float red[8][8][WAY];
    if (lane == 0)
#pragma unroll
        for (int qi = 0; qi < 8; qi++)
#pragma unroll
            for (int c = 0; c < WAY; c++) red[warp][qi][c] = acc[qi][c];
    __syncthreads();

    if (tid < 8 * WAY) {
        int qi = tid / WAY, c = tid % WAY;
        float s = 0.f;
#pragma unroll
        for (int w = 0; w < 8; w++) s += red[w][qi][c];
        atomicAdd(&g_S2[c][q0 + qi], s);
    }
}

// ---------------------------------------------------------------------------
// K4: logits. One warp per query; class counts + S1 computed inline.
// ---------------------------------------------------------------------------
__global__ void logits_kernel(const long long* __restrict__ labels,
                              float* __restrict__ out)
{
    int warp = (blockIdx.x * blockDim.x + threadIdx.x) >> 5;
    int lane = threadIdx.x & 31;
    if (warp >= NQ) return;
    const int q = warp;

    float s1[WAY] = {0.f, 0.f, 0.f, 0.f, 0.f};
    float cnt[WAY] = {0.f, 0.f, 0.f, 0.f, 0.f};
    const float* qb = g_bar[NS + q];

    for (int s = 0; s < NS; s++) {
        const int c = (int)labels[s];
        cnt[c] += 1.f;
        const float* sb = g_bar[s];
        float d = 0.f;
#pragma unroll 4
        for (int k = lane; k < DD; k += 32) d += sb[k] * qb[k];
        s1[c] += d;
    }
#pragma unroll
    for (int o = 16; o; o >>= 1)
#pragma unroll
        for (int c = 0; c < WAY; c++)
            s1[c] += __shfl_xor_sync(0xFFFFFFFFu, s1[c], o);

    if (lane < WAY) {
        int c = lane;
        out[q * WAY + c] = -2.f * (float)(FF * FF) + (4.f * s1[c] - 2.f * g_S2[c][q]) / cnt[c];
    }
}

// ---------------------------------------------------------------------------
extern "C" void kernel_launch(void* const* d_in, const int* in_sizes, int n_in,
                              void* d_out, int out_size)
{
    const float*     sg  = (const float*)d_in[0];
    const float*     sl  = (const float*)d_in[1];
    const long long* lab = (const long long*)d_in[2];
    const float*     qg  = (const float*)d_in[3];
    const float*     ql  = (const float*)d_in[4];
    float*           out = (float*)d_out;

    const int smem = 2 * 2 * SLICE * 2;   // 2 stages x 2 slices = 87040 B
    static bool attr_set = false;
    if (!attr_set) {
        cudaFuncSetAttribute(gram_kernel, cudaFuncAttributeMaxDynamicSharedMemorySize, smem);
        attr_set = true;
    }

    norm_kernel<<<NITEM, 256>>>(sg, sl, qg, ql);   // zero + normalize + rowsum
    gram_kernel<<<GGRID, 256, smem>>>(lab);        // persistent, 2250 units
    dot_kernel<<<dim3(40, 25), 256>>>();           // 1000 CTAs
    logits_kernel<<<(NQ * 32 + 255) / 256, 256>>>(lab, out);
}

// round 10
// speedup vs baseline: 1.3430x; 1.3430x over previous
#include <cuda_runtime.h>
#include <cuda_fp16.h>
#include <cstdint>

#define NS     25
#define NQ     200
#define NITEM  (NS + NQ)        // 225
#define FF     80
#define DD     512
#define WAY    5
#define BLK    128
#define NBLK   10               // packed upper-tri 128x128 blocks of 4x4 grid
#define BLKSZ  (BLK * BLK)      // 16384 halves per block
#define KPACK  (NBLK * BLKSZ)   // 163840
#define PITCH  136              // smem pitch (halves) for X slices
#define SLICE  (FF * PITCH)     // halves per slice buffer
#define NUNIT  (NBLK * (WAY + NQ))   // 2050 units: (class|query, block)
#define GGRID  296              // persistent CTAs (2/SM)

// -------- scratch (__device__ globals; no allocations allowed) --------------
__device__ __half g_Sn[NS * FF * DD];        // 2 MB   normalized supports
__device__ __half g_Qn[NQ * FF * DD];        // 16.4MB normalized queries
__device__ __half g_Gp[WAY][KPACK];          // class Grams fp16, frag order, x2 offdiag
__device__ __half g_Hp[NQ][KPACK];           // query Grams fp16, frag order
__device__ float  g_bar[NITEM][DD];          // per-item feature-row sums
__device__ float  g_sbarsum[WAY][DD];
__device__ int    g_cls_cnt[WAY];
__device__ int    g_cls_sup[WAY][NS];
__device__ float  g_S2[WAY][NQ];

__constant__ int c_bi[NBLK] = {0,0,0,0,1,1,1,2,2,3};
__constant__ int c_bj[NBLK] = {0,1,2,3,1,2,3,2,3,3};

// ---------------------------------------------------------------------------
// K1 (fused): per-item normalize + rowsum. One CTA per item.
// ---------------------------------------------------------------------------
__global__ void __launch_bounds__(256) norm_kernel(
    const float* __restrict__ sg, const float* __restrict__ sl,
    const float* __restrict__ qg, const float* __restrict__ ql)
{
    __shared__ float snorm[FF];
    const int item = blockIdx.x;
    const int tid  = threadIdx.x;
    const int lane = tid & 31;
    const int warp = tid >> 5;

    const float* gbase;
    const float* lbase;
    __half* dst;
    if (item < NS) {
        gbase = sg + (size_t)item * 16 * DD;
        lbase = sl + (size_t)item * 64 * DD;
        dst   = g_Sn + (size_t)item * FF * DD;
    } else {
        int q = item - NS;
        gbase = qg + (size_t)q * 16 * DD;
        lbase = ql + (size_t)q * 64 * DD;
        dst   = g_Qn + (size_t)q * FF * DD;
    }

    for (int f = warp; f < FF; f += 8) {
        const float4* src = (const float4*)((f < 16) ? gbase + (size_t)f * DD
                                                     : lbase + (size_t)(f - 16) * DD);
        float ss = 0.f;
#pragma unroll
        for (int i = 0; i < 4; i++) {
            float4 v = src[lane + 32 * i];
            ss += v.x * v.x + v.y * v.y + v.z * v.z + v.w * v.w;
        }
#pragma unroll
        for (int o = 16; o; o >>= 1) ss += __shfl_xor_sync(0xFFFFFFFFu, ss, o);
        if (lane == 0) snorm[f] = rsqrtf(fmaxf(ss, 1e-24f));
    }
    __syncthreads();

    float sx = 0.f, sy = 0.f;
#pragma unroll 4
    for (int f = 0; f < FF; f++) {
        const float2* src = (const float2*)((f < 16) ? gbase + (size_t)f * DD
                                                     : lbase + (size_t)(f - 16) * DD);
        float2 v = src[tid];
        float rn = snorm[f];
        float a = v.x * rn, b = v.y * rn;
        sx += a; sy += b;
        *(__half2*)(dst + (size_t)f * DD + 2 * tid) = __floats2half2_rn(a, b);
    }
    g_bar[item][2 * tid + 0] = sx;
    g_bar[item][2 * tid + 1] = sy;
}

// ---------------------------------------------------------------------------
// K2: class lists, class-summed row-sums, zero S2 (proven)
// ---------------------------------------------------------------------------
__global__ void prep_kernel(const long long* __restrict__ labels)
{
    __shared__ int cnt[WAY];
    __shared__ int sup[WAY][NS];
    int t = threadIdx.x;  // 512
    if (t == 0) {
        for (int c = 0; c < WAY; c++) cnt[c] = 0;
        for (int s = 0; s < NS; s++) {
            int c = (int)labels[s];
            sup[c][cnt[c]++] = s;
        }
        for (int c = 0; c < WAY; c++) {
            g_cls_cnt[c] = cnt[c];
            for (int i = 0; i < cnt[c]; i++) g_cls_sup[c][i] = sup[c][i];
        }
    }
    __syncthreads();
    if (t < DD) {
#pragma unroll
        for (int c = 0; c < WAY; c++) {
            float a = 0.f;
            for (int i = 0; i < cnt[c]; i++) a += g_bar[sup[c][i]][t];
            g_sbarsum[c][t] = a;
        }
    }
    for (int i = t; i < WAY * NQ; i += blockDim.x)
        (&g_S2[0][0])[i] = 0.f;
}

// ---------------------------------------------------------------------------
// shared mma machinery
// ---------------------------------------------------------------------------
__device__ __forceinline__ void ldsm_x4_t(uint32_t (&r)[4], const __half* p)
{
    uint32_t a = (uint32_t)__cvta_generic_to_shared(p);
    asm volatile("ldmatrix.sync.aligned.m8n8.x4.trans.shared.b16 {%0,%1,%2,%3}, [%4];"
                 : "=r"(r[0]), "=r"(r[1]), "=r"(r[2]), "=r"(r[3]) : "r"(a));
}

__device__ __forceinline__ void mma16816(float (&d)[4], const uint32_t (&a)[4],
                                         uint32_t b0, uint32_t b1)
{
    asm volatile("mma.sync.aligned.m16n8k16.row.col.f32.f16.f16.f32 "
                 "{%0,%1,%2,%3},{%4,%5,%6,%7},{%8,%9},{%0,%1,%2,%3};"
                 : "+f"(d[0]), "+f"(d[1]), "+f"(d[2]), "+f"(d[3])
                 : "r"(a[0]), "r"(a[1]), "r"(a[2]), "r"(a[3]), "r"(b0), "r"(b1));
}

__device__ __forceinline__ void gram_block_mma(
    const __half* sX0, const __half* pB, float (&acc)[2][8][4],
    int m_base, int n_base, int lane)
{
    const int a_krow = ((lane >> 4) << 3) + (lane & 7);
    const int a_coff = ((lane >> 3) & 1) << 3;
    const int b_krow = (((lane >> 3) & 1) << 3) + (lane & 7);
    const int b_coff = (lane >> 4) << 3;

#pragma unroll
    for (int k16 = 0; k16 < FF / 16; k16++) {
        const int k0 = k16 * 16;
        uint32_t a[2][4];
#pragma unroll
        for (int mt = 0; mt < 2; mt++)
            ldsm_x4_t(a[mt], &sX0[(k0 + a_krow) * PITCH + m_base + mt * 16 + a_coff]);
#pragma unroll
        for (int nt = 0; nt < 4; nt++) {
            uint32_t bf[4];
            ldsm_x4_t(bf, &pB[(k0 + b_krow) * PITCH + n_base + nt * 16 + b_coff]);
#pragma unroll
            for (int mt = 0; mt < 2; mt++) {
                mma16816(acc[mt][2 * nt + 0], a[mt], bf[0], bf[1]);
                mma16816(acc[mt][2 * nt + 1], a[mt], bf[2], bf[3]);
            }
        }
    }
}

// ---------------------------------------------------------------------------
// K3: persistent pipelined Gram kernel over 2050 units = (class|query, block).
// Support units (item < WAY) loop over class members, accumulating in fp32
// regs; pipeline iterator walks (unit, member) pairs so prefetch never stalls.
// ---------------------------------------------------------------------------
extern __shared__ char dynsmem[];

__device__ __forceinline__ const __half* member_base(
    int item, int m, const int s_sup[WAY][NS])
{
    return (item < WAY) ? g_Sn + (size_t)s_sup[item][m] * FF * DD
                        : g_Qn + (size_t)(item - WAY) * FF * DD;
}

__device__ __forceinline__ void issue_tile_load(
    const __half* base, int b, int stage, int tid)
{
    const int bi = c_bi[b], bj = c_bj[b];
    __half* s0 = (__half*)dynsmem + stage * 2 * SLICE;
    const int nch = (bi == bj) ? 1280 : 2560;
    for (int ch = tid; ch < nch; ch += 256) {
        int tile = (ch >= 1280) ? 1 : 0;
        int rem  = ch - tile * 1280;
        int r = rem >> 4, cc = rem & 15;
        int colblk = tile ? bj : bi;
        const __half* src = base + (size_t)r * DD + colblk * 128 + cc * 8;
        __half* dsts = s0 + tile * SLICE + r * PITCH + cc * 8;
        uint32_t dst = (uint32_t)__cvta_generic_to_shared(dsts);
        asm volatile("cp.async.cg.shared.global [%0], [%1], 16;" :: "r"(dst), "l"(src));
    }
    asm volatile("cp.async.commit_group;");
}

__global__ void __launch_bounds__(256, 2) gram_kernel()
{
    __shared__ int s_cnt[WAY];
    __shared__ int s_sup[WAY][NS];

    const int tid  = threadIdx.x;
    const int lane = tid & 31;
    const int warp = tid >> 5;
    const int m_base = (warp >> 1) * 32;
    const int n_base = (warp & 1) * 64;

    if (tid < WAY) s_cnt[tid] = g_cls_cnt[tid];
    if (tid < WAY * NS) (&s_sup[0][0])[tid] = (&g_cls_sup[0][0])[tid];
    __syncthreads();

    int cu = blockIdx.x, cm = 0;
    if (cu >= NUNIT) return;

    issue_tile_load(member_base(cu / NBLK, 0, s_sup), cu % NBLK, 0, tid);
    int stage = 0;

    float acc[2][8][4];
#pragma unroll
    for (int mt = 0; mt < 2; mt++)
#pragma unroll
        for (int nt = 0; nt < 8; nt++)
#pragma unroll
            for (int i = 0; i < 4; i++) acc[mt][nt][i] = 0.f;

    while (cu < NUNIT) {
        const int item = cu / NBLK, b = cu % NBLK;
        const int mcnt = (item < WAY) ? s_cnt[item] : 1;

        // next (unit, member) in this CTA's sequence
        int nu = cu, nm = cm + 1;
        if (nm >= mcnt) { nu = cu + gridDim.x; nm = 0; }

        if (nu < NUNIT) {
            issue_tile_load(member_base(nu / NBLK, nm, s_sup), nu % NBLK, stage ^ 1, tid);
            asm volatile("cp.async.wait_group 1;");
        } else {
            asm volatile("cp.async.wait_group 0;");
        }
        __syncthreads();

        const bool diag = (c_bi[b] == c_bj[b]);
        const __half* s0 = (const __half*)dynsmem + stage * 2 * SLICE;
        const __half* pB = diag ? s0 : s0 + SLICE;

        gram_block_mma(s0, pB, acc, m_base, n_base, lane);

        if (cm == mcnt - 1) {
            // epilogue: fragment-order coalesced fp16 store, class-scale baked in
            const float scale = (item < WAY && !diag) ? 2.f : 1.f;
            __half* out = ((item < WAY) ? g_Gp[item] : g_Hp[item - WAY]) + (size_t)b * BLKSZ;
#pragma unroll
            for (int j = 0; j < 8; j++) {
                const int mt = j >> 2, nt0 = (j & 3) * 2;
                __half2 h[4];
                h[0] = __floats2half2_rn(acc[mt][nt0][0] * scale, acc[mt][nt0][1] * scale);
                h[1] = __floats2half2_rn(acc[mt][nt0][2] * scale, acc[mt][nt0][3] * scale);
                h[2] = __floats2half2_rn(acc[mt][nt0 + 1][0] * scale, acc[mt][nt0 + 1][1] * scale);
                h[3] = __floats2half2_rn(acc[mt][nt0 + 1][2] * scale, acc[mt][nt0 + 1][3] * scale);
                *(int4*)(out + (size_t)(j * 256 + tid) * 8) = *(int4*)h;
            }
            // reset accumulators for next unit
#pragma unroll
            for (int mt = 0; mt < 2; mt++)
#pragma unroll
                for (int nt = 0; nt < 8; nt++)
#pragma unroll
                    for (int i = 0; i < 4; i++) acc[mt][nt][i] = 0.f;
        }
        __syncthreads();
        stage ^= 1;
        cu = nu; cm = nm;
    }
}

// ---------------------------------------------------------------------------
// K4: dot (proven coalesced form). grid (40 kchunks x 25 query-octets).
// ---------------------------------------------------------------------------
__global__ void __launch_bounds__(256) dot_kernel()
{
    const int kc   = blockIdx.x;            // 0..39
    const int q0   = blockIdx.y * 8;        // 0..192
    const int tid  = threadIdx.x;
    const int lane = tid & 31;
    const int warp = tid >> 5;
    const int kbase = kc * 4096 + warp * 512 + lane * 8;

    __half2 G[WAY][8];
#pragma unroll
    for (int c = 0; c < WAY; c++) {
        *(int4*)&G[c][0] = *(const int4*)&g_Gp[c][kbase];
        *(int4*)&G[c][4] = *(const int4*)&g_Gp[c][kbase + 256];
    }

    float acc[8][WAY];
#pragma unroll
    for (int qi = 0; qi < 8; qi++)
#pragma unroll
        for (int c = 0; c < WAY; c++) acc[qi][c] = 0.f;

#pragma unroll
    for (int qi = 0; qi < 8; qi++) {
        const __half* Hq = g_Hp[q0 + qi] + kbase;
        __half2 H[8];
        *(int4*)&H[0] = *(const int4*)(Hq);
        *(int4*)&H[4] = *(const int4*)(Hq + 256);
#pragma unroll
        for (int c = 0; c < WAY; c++) {
            __half2 a = __hmul2(G[c][0], H[0]);
#pragma unroll
            for (int j = 1; j < 8; j++) a = __hfma2(G[c][j], H[j], a);
            float2 f = __half22float2(a);
            acc[qi][c] = f.x + f.y;
        }
    }

#pragma unroll
    for (int o = 16; o; o >>= 1)
#pragma unroll
        for (int qi = 0; qi < 8; qi++)
#pragma unroll
            for (int c = 0; c < WAY; c++)
                acc[qi][c] += __shfl_xor_sync(0xFFFFFFFFu, acc[qi][c], o);

    __shared__ float red[8][8][WAY];
    if (lane == 0)
#pragma unroll
        for (int qi = 0; qi < 8; qi++)
#pragma unroll
            for (int c = 0; c < WAY; c++) red[warp][qi][c] = acc[qi][c];
    __syncthreads();

    if (tid < 8 * WAY) {
        int qi = tid / WAY, c = tid % WAY;
        float s = 0.f;
#pragma unroll
        for (int w = 0; w < 8; w++) s += red[w][qi][c];
        atomicAdd(&g_S2[c][q0 + qi], s);
    }
}

// ---------------------------------------------------------------------------
// K5: logits (proven fast form, sbarsum precomputed)
// ---------------------------------------------------------------------------
__global__ void logits_kernel(float* __restrict__ out)
{
    int warp = (blockIdx.x * blockDim.x + threadIdx.x) >> 5;
    int lane = threadIdx.x & 31;
    if (warp >= NQ) return;
    const int q = warp;

    float s1[WAY] = {0.f, 0.f, 0.f, 0.f, 0.f};
    const float* qb = g_bar[NS + q];
    for (int k = lane; k < DD; k += 32) {
        float qv = qb[k];
#pragma unroll
        for (int c = 0; c < WAY; c++) s1[c] += g_sbarsum[c][k] * qv;
    }
#pragma unroll
    for (int o = 16; o; o >>= 1)
#pragma unroll
        for (int c = 0; c < WAY; c++)
            s1[c] += __shfl_xor_sync(0xFFFFFFFFu, s1[c], o);

    if (lane < WAY) {
        int c = lane;
        float cnt = (float)g_cls_cnt[c];
        out[q * WAY + c] = -2.f * (float)(FF * FF) + (4.f * s1[c] - 2.f * g_S2[c][q]) / cnt;
    }
}

// ---------------------------------------------------------------------------
extern "C" void kernel_launch(void* const* d_in, const int* in_sizes, int n_in,
                              void* d_out, int out_size)
{
    const float*     sg  = (const float*)d_in[0];
    const float*     sl  = (const float*)d_in[1];
    const long long* lab = (const long long*)d_in[2];
    const float*     qg  = (const float*)d_in[3];
    const float*     ql  = (const float*)d_in[4];
    float*           out = (float*)d_out;

    const int smem = 2 * 2 * SLICE * 2;   // 2 stages x 2 slices = 87040 B
    static bool attr_set = false;
    if (!attr_set) {
        cudaFuncSetAttribute(gram_kernel, cudaFuncAttributeMaxDynamicSharedMemorySize, smem);
        attr_set = true;
    }

    norm_kernel<<<NITEM, 256>>>(sg, sl, qg, ql);   // normalize + rowsum
    prep_kernel<<<1, 512>>>(lab);
    gram_kernel<<<GGRID, 256, smem>>>();           // persistent, 2050 units
    dot_kernel<<<dim3(40, 25), 256>>>();           // 1000 CTAs
    logits_kernel<<<(NQ * 32 + 255) / 256, 256>>>(out);
}

// round 11
// speedup vs baseline: 1.4754x; 1.0986x over previous
#include <cuda_runtime.h>
#include <cuda_fp16.h>
#include <cstdint>

#define NS     25
#define NQ     200
#define NITEM  (NS + NQ)        // 225
#define FF     80
#define DD     512
#define WAY    5
#define BLK    128
#define NBLK   10               // packed upper-tri 128x128 blocks of 4x4 grid
#define BLKSZ  (BLK * BLK)      // 16384 halves per block
#define KPACK  (NBLK * BLKSZ)   // 163840
#define PITCH  136              // smem pitch (halves) for X slices
#define SLICE  (FF * PITCH)     // halves per slice buffer
#define NUNIT  (NBLK * NITEM)   // 2250
#define GGRID  296              // persistent CTAs (2/SM)

// -------- scratch (__device__ globals; no allocations allowed) --------------
__device__ __half g_Sn[NS * FF * DD];        // 2 MB   normalized supports
__device__ __half g_Qn[NQ * FF * DD];        // 16.4MB normalized queries
__device__ __half g_Gs[NS][KPACK];           // per-support Grams, frag order (x2 offdiag)
__device__ __half g_Gp[WAY][KPACK];          // class-summed Grams, frag order
__device__ __half g_Hp[NQ][KPACK];           // query Grams, frag order
__device__ float  g_bar[NITEM][DD];          // per-item feature-row sums
__device__ float  g_sbarsum[WAY][DD];
__device__ int    g_cls_cnt[WAY];
__device__ float  g_S2[WAY][NQ];

__constant__ int c_bi[NBLK] = {0,0,0,0,1,1,1,2,2,3};
__constant__ int c_bj[NBLK] = {0,1,2,3,1,2,3,2,3,3};

// ---------------------------------------------------------------------------
// K1 (fused): per-item normalize + rowsum. One CTA per item. (proven ~8.5us)
// ---------------------------------------------------------------------------
__global__ void __launch_bounds__(256) norm_kernel(
    const float* __restrict__ sg, const float* __restrict__ sl,
    const float* __restrict__ qg, const float* __restrict__ ql)
{
    __shared__ float snorm[FF];
    const int item = blockIdx.x;
    const int tid  = threadIdx.x;
    const int lane = tid & 31;
    const int warp = tid >> 5;

    const float* gbase;
    const float* lbase;
    __half* dst;
    if (item < NS) {
        gbase = sg + (size_t)item * 16 * DD;
        lbase = sl + (size_t)item * 64 * DD;
        dst   = g_Sn + (size_t)item * FF * DD;
    } else {
        int q = item - NS;
        gbase = qg + (size_t)q * 16 * DD;
        lbase = ql + (size_t)q * 64 * DD;
        dst   = g_Qn + (size_t)q * FF * DD;
    }

    for (int f = warp; f < FF; f += 8) {
        const float4* src = (const float4*)((f < 16) ? gbase + (size_t)f * DD
                                                     : lbase + (size_t)(f - 16) * DD);
        float ss = 0.f;
#pragma unroll
        for (int i = 0; i < 4; i++) {
            float4 v = src[lane + 32 * i];
            ss += v.x * v.x + v.y * v.y + v.z * v.z + v.w * v.w;
        }
#pragma unroll
        for (int o = 16; o; o >>= 1) ss += __shfl_xor_sync(0xFFFFFFFFu, ss, o);
        if (lane == 0) snorm[f] = rsqrtf(fmaxf(ss, 1e-24f));
    }
    __syncthreads();

    float sx = 0.f, sy = 0.f;
#pragma unroll 4
    for (int f = 0; f < FF; f++) {
        const float2* src = (const float2*)((f < 16) ? gbase + (size_t)f * DD
                                                     : lbase + (size_t)(f - 16) * DD);
        float2 v = src[tid];
        float rn = snorm[f];
        float a = v.x * rn, b = v.y * rn;
        sx += a; sy += b;
        *(__half2*)(dst + (size_t)f * DD + 2 * tid) = __floats2half2_rn(a, b);
    }
    g_bar[item][2 * tid + 0] = sx;
    g_bar[item][2 * tid + 1] = sy;
}

// ---------------------------------------------------------------------------
// K2: class counts, class-summed row-sums, zero S2 (proven ~0.8us)
// ---------------------------------------------------------------------------
__global__ void prep_kernel(const long long* __restrict__ labels)
{
    __shared__ int cnt[WAY];
    __shared__ int sup[WAY][NS];
    int t = threadIdx.x;  // 512
    if (t == 0) {
        for (int c = 0; c < WAY; c++) cnt[c] = 0;
        for (int s = 0; s < NS; s++) {
            int c = (int)labels[s];
            sup[c][cnt[c]++] = s;
        }
        for (int c = 0; c < WAY; c++) g_cls_cnt[c] = cnt[c];
    }
    __syncthreads();
    if (t < DD) {
#pragma unroll
        for (int c = 0; c < WAY; c++) {
            float a = 0.f;
            for (int i = 0; i < cnt[c]; i++) a += g_bar[sup[c][i]][t];
            g_sbarsum[c][t] = a;
        }
    }
    for (int i = t; i < WAY * NQ; i += blockDim.x)
        (&g_S2[0][0])[i] = 0.f;
}

// ---------------------------------------------------------------------------
// shared mma machinery
// ---------------------------------------------------------------------------
__device__ __forceinline__ void ldsm_x4_t(uint32_t (&r)[4], const __half* p)
{
    uint32_t a = (uint32_t)__cvta_generic_to_shared(p);
    asm volatile("ldmatrix.sync.aligned.m8n8.x4.trans.shared.b16 {%0,%1,%2,%3}, [%4];"
                 : "=r"(r[0]), "=r"(r[1]), "=r"(r[2]), "=r"(r[3]) : "r"(a));
}

__device__ __forceinline__ void mma16816(float (&d)[4], const uint32_t (&a)[4],
                                         uint32_t b0, uint32_t b1)
{
    asm volatile("mma.sync.aligned.m16n8k16.row.col.f32.f16.f16.f32 "
                 "{%0,%1,%2,%3},{%4,%5,%6,%7},{%8,%9},{%0,%1,%2,%3};"
                 : "+f"(d[0]), "+f"(d[1]), "+f"(d[2]), "+f"(d[3])
                 : "r"(a[0]), "r"(a[1]), "r"(a[2]), "r"(a[3]), "r"(b0), "r"(b1));
}

__device__ __forceinline__ void gram_block_mma(
    const __half* sX0, const __half* pB, float (&acc)[2][8][4],
    int m_base, int n_base, int lane)
{
    const int a_krow = ((lane >> 4) << 3) + (lane & 7);
    const int a_coff = ((lane >> 3) & 1) << 3;
    const int b_krow = (((lane >> 3) & 1) << 3) + (lane & 7);
    const int b_coff = (lane >> 4) << 3;

#pragma unroll
    for (int k16 = 0; k16 < FF / 16; k16++) {
        const int k0 = k16 * 16;
        uint32_t a[2][4];
#pragma unroll
        for (int mt = 0; mt < 2; mt++)
            ldsm_x4_t(a[mt], &sX0[(k0 + a_krow) * PITCH + m_base + mt * 16 + a_coff]);
#pragma unroll
        for (int nt = 0; nt < 4; nt++) {
            uint32_t bf[4];
            ldsm_x4_t(bf, &pB[(k0 + b_krow) * PITCH + n_base + nt * 16 + b_coff]);
#pragma unroll
            for (int mt = 0; mt < 2; mt++) {
                mma16816(acc[mt][2 * nt + 0], a[mt], bf[0], bf[1]);
                mma16816(acc[mt][2 * nt + 1], a[mt], bf[2], bf[3]);
            }
        }
    }
}

// ---------------------------------------------------------------------------
// K3: persistent pipelined Gram kernel (R7 exact form, 27.7us proven).
// 2250 units = (item, block). Per-support -> g_Gs, query -> g_Hp.
// ---------------------------------------------------------------------------
extern __shared__ char dynsmem[];

__device__ __forceinline__ void issue_unit_load(int u, int stage, int tid)
{
    const int item = u / NBLK, b = u % NBLK;
    const int bi = c_bi[b], bj = c_bj[b];
    const __half* base = (item < NS) ? g_Sn + (size_t)item * FF * DD
                                     : g_Qn + (size_t)(item - NS) * FF * DD;
    __half* s0 = (__half*)dynsmem + stage * 2 * SLICE;
    const int nch = (bi == bj) ? 1280 : 2560;
    for (int ch = tid; ch < nch; ch += 256) {
        int tile = (ch >= 1280) ? 1 : 0;
        int rem  = ch - tile * 1280;
        int r = rem >> 4, cc = rem & 15;
        int colblk = tile ? bj : bi;
        const __half* src = base + (size_t)r * DD + colblk * 128 + cc * 8;
        __half* dsts = s0 + tile * SLICE + r * PITCH + cc * 8;
        uint32_t dst = (uint32_t)__cvta_generic_to_shared(dsts);
        asm volatile("cp.async.cg.shared.global [%0], [%1], 16;" :: "r"(dst), "l"(src));
    }
    asm volatile("cp.async.commit_group;");
}

__global__ void __launch_bounds__(256, 2) gram_kernel()
{
    const int tid  = threadIdx.x;
    const int lane = tid & 31;
    const int warp = tid >> 5;
    const int m_base = (warp >> 1) * 32;
    const int n_base = (warp & 1) * 64;

    int u = blockIdx.x;
    if (u >= NUNIT) return;

    issue_unit_load(u, 0, tid);
    int stage = 0;

    for (; u < NUNIT; u += gridDim.x) {
        const int nextu = u + gridDim.x;
        if (nextu < NUNIT) {
            issue_unit_load(nextu, stage ^ 1, tid);
            asm volatile("cp.async.wait_group 1;");
        } else {
            asm volatile("cp.async.wait_group 0;");
        }
        __syncthreads();

        const int item = u / NBLK, b = u % NBLK;
        const bool diag = (c_bi[b] == c_bj[b]);
        const __half* s0 = (const __half*)dynsmem + stage * 2 * SLICE;
        const __half* pB = diag ? s0 : s0 + SLICE;

        float acc[2][8][4];
#pragma unroll
        for (int mt = 0; mt < 2; mt++)
#pragma unroll
            for (int nt = 0; nt < 8; nt++)
#pragma unroll
                for (int i = 0; i < 4; i++) acc[mt][nt][i] = 0.f;

        gram_block_mma(s0, pB, acc, m_base, n_base, lane);

        const float scale = (item < NS && !diag) ? 2.f : 1.f;
        __half* out = ((item < NS) ? g_Gs[item] : g_Hp[item - NS]) + (size_t)b * BLKSZ;
#pragma unroll
        for (int j = 0; j < 8; j++) {
            const int mt = j >> 2, nt0 = (j & 3) * 2;
            __half2 h[4];
            h[0] = __floats2half2_rn(acc[mt][nt0][0] * scale, acc[mt][nt0][1] * scale);
            h[1] = __floats2half2_rn(acc[mt][nt0][2] * scale, acc[mt][nt0][3] * scale);
            h[2] = __floats2half2_rn(acc[mt][nt0 + 1][0] * scale, acc[mt][nt0 + 1][1] * scale);
            h[3] = __floats2half2_rn(acc[mt][nt0 + 1][2] * scale, acc[mt][nt0 + 1][3] * scale);
            *(int4*)(out + (size_t)(j * 256 + tid) * 8) = *(int4*)h;
        }
        __syncthreads();
        stage ^= 1;
    }
}

// ---------------------------------------------------------------------------
// K4: classsum v2 — compile-time NS loop, unroll-5 (5 loads in flight),
// predication-free class select via indicator weights. grid = 80 CTAs.
// ---------------------------------------------------------------------------
__global__ void __launch_bounds__(256) classsum_kernel(const long long* __restrict__ labels)
{
    __shared__ float ind[NS][WAY];
    const int tid = threadIdx.x;
    if (tid < NS * WAY) {
        int s = tid / WAY, c = tid % WAY;
        ind[s][c] = ((int)labels[s] == c) ? 1.f : 0.f;
    }
    __syncthreads();

    const int base = blockIdx.x * 2048 + tid * 8;

    float acc[WAY][8];
#pragma unroll
    for (int c = 0; c < WAY; c++)
#pragma unroll
        for (int j = 0; j < 8; j++) acc[c][j] = 0.f;

#pragma unroll 5
    for (int s = 0; s < NS; s++) {
        int4 v = *(const int4*)&g_Gs[s][base];
        const __half2* h = (const __half2*)&v;
        float f[8];
#pragma unroll
        for (int j = 0; j < 4; j++) {
            float2 p = __half22float2(h[j]);
            f[2 * j] = p.x; f[2 * j + 1] = p.y;
        }
#pragma unroll
        for (int c = 0; c < WAY; c++) {
            const float w = ind[s][c];
#pragma unroll
            for (int j = 0; j < 8; j++) acc[c][j] += f[j] * w;
        }
    }

#pragma unroll
    for (int c = 0; c < WAY; c++) {
        __half2 o[4];
#pragma unroll
        for (int j = 0; j < 4; j++) o[j] = __floats2half2_rn(acc[c][2 * j], acc[c][2 * j + 1]);
        *(int4*)&g_Gp[c][base] = *(int4*)o;
    }
}

// ---------------------------------------------------------------------------
// K5: dot (R10 form, 21.8us measured). grid (40 kchunks x 25 query-octets).
// ---------------------------------------------------------------------------
__global__ void __launch_bounds__(256) dot_kernel()
{
    const int kc   = blockIdx.x;            // 0..39
    const int q0   = blockIdx.y * 8;        // 0..192
    const int tid  = threadIdx.x;
    const int lane = tid & 31;
    const int warp = tid >> 5;
    const int kbase = kc * 4096 + warp * 512 + lane * 8;

    __half2 G[WAY][8];
#pragma unroll
    for (int c = 0; c < WAY; c++) {
        *(int4*)&G[c][0] = *(const int4*)&g_Gp[c][kbase];
        *(int4*)&G[c][4] = *(const int4*)&g_Gp[c][kbase + 256];
    }

    float acc[8][WAY];
#pragma unroll
    for (int qi = 0; qi < 8; qi++)
#pragma unroll
        for (int c = 0; c < WAY; c++) acc[qi][c] = 0.f;

#pragma unroll
    for (int qi = 0; qi < 8; qi++) {
        const __half* Hq = g_Hp[q0 + qi] + kbase;
        __half2 H[8];
        *(int4*)&H[0] = *(const int4*)(Hq);
        *(int4*)&H[4] = *(const int4*)(Hq + 256);
#pragma unroll
        for (int c = 0; c < WAY; c++) {
            __half2 a = __hmul2(G[c][0], H[0]);
#pragma unroll
            for (int j = 1; j < 8; j++) a = __hfma2(G[c][j], H[j], a);
            float2 f = __half22float2(a);
            acc[qi][c] = f.x + f.y;
        }
    }

#pragma unroll
    for (int o = 16; o; o >>= 1)
#pragma unroll
        for (int qi = 0; qi < 8; qi++)
#pragma unroll
            for (int c = 0; c < WAY; c++)
                acc[qi][c] += __shfl_xor_sync(0xFFFFFFFFu, acc[qi][c], o);

    __shared__ float red[8][8][WAY];
    if (lane == 0)
#pragma unroll
        for (int qi = 0; qi < 8; qi++)
#pragma unroll
            for (int c = 0; c < WAY; c++) red[warp][qi][c] = acc[qi][c];
    __syncthreads();

    if (tid < 8 * WAY) {
        int qi = tid / WAY, c = tid % WAY;
        float s = 0.f;
#pragma unroll
        for (int w = 0; w < 8; w++) s += red[w][qi][c];
        atomicAdd(&g_S2[c][q0 + qi], s);
    }
}

// ---------------------------------------------------------------------------
// K6: logits (proven fast form)
// ---------------------------------------------------------------------------
__global__ void logits_kernel(float* __restrict__ out)
{
    int warp = (blockIdx.x * blockDim.x + threadIdx.x) >> 5;
    int lane = threadIdx.x & 31;
    if (warp >= NQ) return;
    const int q = warp;

    float s1[WAY] = {0.f, 0.f, 0.f, 0.f, 0.f};
    const float* qb = g_bar[NS + q];
    for (int k = lane; k < DD; k += 32) {
        float qv = qb[k];
#pragma unroll
        for (int c = 0; c < WAY; c++) s1[c] += g_sbarsum[c][k] * qv;
    }
#pragma unroll
    for (int o = 16; o; o >>= 1)
#pragma unroll
        for (int c = 0; c < WAY; c++)
            s1[c] += __shfl_xor_sync(0xFFFFFFFFu, s1[c], o);

    if (lane < WAY) {
        int c = lane;
        float cnt = (float)g_cls_cnt[c];
        out[q * WAY + c] = -2.f * (float)(FF * FF) + (4.f * s1[c] - 2.f * g_S2[c][q]) / cnt;
    }
}

// ---------------------------------------------------------------------------
extern "C" void kernel_launch(void* const* d_in, const int* in_sizes, int n_in,
                              void* d_out, int out_size)
{
    const float*     sg  = (const float*)d_in[0];
    const float*     sl  = (const float*)d_in[1];
    const long long* lab = (const long long*)d_in[2];
    const float*     qg  = (const float*)d_in[3];
    const float*     ql  = (const float*)d_in[4];
    float*           out = (float*)d_out;

    const int smem = 2 * 2 * SLICE * 2;   // 2 stages x 2 slices = 87040 B
    static bool attr_set = false;
    if (!attr_set) {
        cudaFuncSetAttribute(gram_kernel, cudaFuncAttributeMaxDynamicSharedMemorySize, smem);
        attr_set = true;
    }

    norm_kernel<<<NITEM, 256>>>(sg, sl, qg, ql);       // normalize + rowsum
    prep_kernel<<<1, 512>>>(lab);
    gram_kernel<<<GGRID, 256, smem>>>();               // persistent, 2250 units (R7 exact)
    classsum_kernel<<<KPACK / 2048, 256>>>(lab);       // 80 CTAs, unroll-5
    dot_kernel<<<dim3(40, 25), 256>>>();               // 1000 CTAs
    logits_kernel<<<(NQ * 32 + 255) / 256, 256>>>(out);
}